// round 8
// baseline (speedup 1.0000x reference)
#include <cuda_runtime.h>
#include <cuda_bf16.h>
#include <math.h>
#include <stdint.h>

// Problem constants
#define BATCH 4
#define SEQ   2048
#define DIM   1024

// GEMM tiling: CTA 128x128x32, 8 warps (4m x 2n), warp tile 32x64, double buffer
#define BM 128
#define BN 128
#define BK 32
#define NTH 256

// smem: bf16 tiles, rows padded to 40 elems (80 B) for conflict-free ldmatrix
#define RSB      80
#define TILE_B   (128 * RSB)             // 10240 B per plane tile
#define OFF_AHI  0
#define OFF_ALO  (1 * TILE_B)
#define OFF_BHI  (2 * TILE_B)
#define OFF_BLO  (3 * TILE_B)
#define STAGE_B  (4 * TILE_B)            // 40960 B
#define SMEM_TOTAL (2 * STAGE_B)         // 81920 B

typedef __nv_bfloat16 bf16;

// ---------------------------------------------------------------------------
// Scratch (device globals — allocation-free per harness rules)
// ---------------------------------------------------------------------------
#define PLANE  ((long)BATCH * SEQ * DIM)     // 8M elems
__device__ bf16  g_xhi[PLANE],  g_xlo[PLANE];
__device__ bf16  g_Whi[3 * DIM * DIM], g_Wlo[3 * DIM * DIM];
__device__ bf16  g_QKVhi[3 * PLANE], g_QKVlo[3 * PLANE];   // Q | K | V planes
__device__ bf16  g_VThi[PLANE], g_VTlo[PLANE];             // per batch [DIM, SEQ]
__device__ float g_S[(size_t)BATCH * SEQ * SEQ];
__device__ bf16  g_Phi[(size_t)BATCH * SEQ * SEQ], g_Plo[(size_t)BATCH * SEQ * SEQ];

// ---------------------------------------------------------------------------
// helpers
// ---------------------------------------------------------------------------
__device__ __forceinline__ uint32_t smem_u32(const void* p) {
    uint32_t a;
    asm("{ .reg .u64 t; cvta.to.shared.u64 t, %1; cvt.u32.u64 %0, t; }"
        : "=r"(a) : "l"(p));
    return a;
}

__device__ __forceinline__ void cpa16(uint32_t dst, const void* src) {
    asm volatile("cp.async.cg.shared.global [%0], [%1], 16;"
                 :: "r"(dst), "l"(src) : "memory");
}
#define CP_COMMIT() asm volatile("cp.async.commit_group;" ::: "memory")
#define CP_WAIT(n)  asm volatile("cp.async.wait_group %0;" :: "n"(n) : "memory")

#define LDSM_X4(r0, r1, r2, r3, addr) \
    asm volatile("ldmatrix.sync.aligned.m8n8.x4.shared.b16 {%0,%1,%2,%3}, [%4];" \
                 : "=r"(r0), "=r"(r1), "=r"(r2), "=r"(r3) : "r"(addr))

#define MMA_BF16(d, a, b) \
    asm volatile("mma.sync.aligned.m16n8k16.row.col.f32.bf16.bf16.f32 " \
                 "{%0,%1,%2,%3}, {%4,%5,%6,%7}, {%8,%9}, {%0,%1,%2,%3};" \
                 : "+f"((d)[0]), "+f"((d)[1]), "+f"((d)[2]), "+f"((d)[3]) \
                 : "r"((a)[0]), "r"((a)[1]), "r"((a)[2]), "r"((a)[3]), \
                   "r"((b)[0]), "r"((b)[1]))

// split 2 floats -> packed bf16x2 (hi) and packed bf16x2 (lo residual)
__device__ __forceinline__ void split_pack2(float a, float b,
                                            uint32_t& hi, uint32_t& lo) {
    __nv_bfloat162 h = __floats2bfloat162_rn(a, b);
    float2 hf = __bfloat1622float2(h);
    __nv_bfloat162 l = __floats2bfloat162_rn(a - hf.x, b - hf.y);
    hi = *reinterpret_cast<uint32_t*>(&h);
    lo = *reinterpret_cast<uint32_t*>(&l);
}

// ---------------------------------------------------------------------------
// bf16 split GEMM (pre-split inputs), double-buffered cp.async:
//   C[M,N] = alpha * (Ahi+Alo)[M,K] * (Bhi+Blo)[N,K]^T   (lo*lo dropped)
// EPI 0: C fp32;  EPI 1: C written as hi/lo bf16 planes.
// CSKIP: skip tiles above causal diagonal. KLIM: K chunks < m0+BM.
// ---------------------------------------------------------------------------
template <bool CSKIP, bool KLIM, int EPI>
__global__ __launch_bounds__(NTH, 1)
void mm_s(const bf16* __restrict__ Ahi, const bf16* __restrict__ Alo,
          const bf16* __restrict__ Bhi, const bf16* __restrict__ Blo,
          float* __restrict__ C, bf16* __restrict__ Chi, bf16* __restrict__ Clo,
          int N, int K, float alpha, long sA, long sB, long sC)
{
    const int bz = blockIdx.z;
    Ahi += (long)bz * sA;  Alo += (long)bz * sA;
    Bhi += (long)bz * sB;  Blo += (long)bz * sB;

    const int m0 = blockIdx.y * BM;
    const int n0 = blockIdx.x * BN;
    if (CSKIP && (m0 + BM - 1 < n0)) return;

    int nch = K / BK;
    if (KLIM) {
        int lim = (m0 + BM) / BK;
        nch = (lim < nch) ? lim : nch;
    }

    extern __shared__ char smem[];
    const uint32_t sb = smem_u32(smem);

    const int tid  = threadIdx.x;
    const int wid  = tid >> 5;
    const int lane = tid & 31;
    const int wm   = wid & 3;       // warp m block (32 rows)  -- proven R3/R4 map
    const int wn   = wid >> 2;      // warp n block (64 cols)

    // cp.async: 512 16B-chunks per plane tile; 2 per thread per plane
    const int rc0 = tid >> 2;            // rows 0..63
    const int oc0 = tid & 3;
    const int rc1 = rc0 + 64;            // rows 64..127

    auto stage_load = [&](int c, int buf) {
        const uint32_t st = sb + buf * STAGE_B;
        const long ck = (long)c * BK + oc0 * 8;
        const long ga0 = (long)(m0 + rc0) * K + ck;
        const long ga1 = (long)(m0 + rc1) * K + ck;
        const long gb0 = (long)(n0 + rc0) * K + ck;
        const long gb1 = (long)(n0 + rc1) * K + ck;
        const uint32_t d0 = rc0 * RSB + oc0 * 16;
        const uint32_t d1 = rc1 * RSB + oc0 * 16;
        cpa16(st + OFF_AHI + d0, Ahi + ga0);
        cpa16(st + OFF_AHI + d1, Ahi + ga1);
        cpa16(st + OFF_ALO + d0, Alo + ga0);
        cpa16(st + OFF_ALO + d1, Alo + ga1);
        cpa16(st + OFF_BHI + d0, Bhi + gb0);
        cpa16(st + OFF_BHI + d1, Bhi + gb1);
        cpa16(st + OFF_BLO + d0, Blo + gb0);
        cpa16(st + OFF_BLO + d1, Blo + gb1);
        CP_COMMIT();
    };

    float acc[2][8][4] = {};

    stage_load(0, 0);

    for (int c = 0; c < nch; c++) {
        const int buf = c & 1;
        if (c + 1 < nch) { stage_load(c + 1, buf ^ 1); CP_WAIT(1); }
        else             { CP_WAIT(0); }
        __syncthreads();

        const uint32_t st = sb + buf * STAGE_B;
        const uint32_t aH = st + OFF_AHI;
        const uint32_t aL = st + OFF_ALO;
        const uint32_t bH = st + OFF_BHI;
        const uint32_t bL = st + OFF_BLO;

        #pragma unroll
        for (int kk = 0; kk < BK; kk += 16) {
            // A fragments: 2 m16 blocks, hi + lo
            uint32_t ahi[2][4], alo[2][4];
            {
                const int arow = wm * 32 + (lane & 15);
                const int akb  = (kk + ((lane >> 4) << 3)) * 2;
                #pragma unroll
                for (int f = 0; f < 2; f++) {
                    const uint32_t addr = (uint32_t)((arow + f * 16) * RSB + akb);
                    LDSM_X4(ahi[f][0], ahi[f][1], ahi[f][2], ahi[f][3], aH + addr);
                    LDSM_X4(alo[f][0], alo[f][1], alo[f][2], alo[f][3], aL + addr);
                }
            }
            // B fragments: all 8 n8 blocks, hi + lo, hoisted for reordering
            uint32_t bhi[8][2], blo[8][2];
            {
                const int g = lane >> 3;
                const int r = lane & 7;
                const int brow0 = wn * 64 + ((g >> 1) << 3) + r;
                const int bkb   = (kk + ((g & 1) << 3)) * 2;
                #pragma unroll
                for (int p = 0; p < 4; p++) {
                    const uint32_t addr = (uint32_t)((brow0 + p * 16) * RSB + bkb);
                    LDSM_X4(bhi[2 * p][0], bhi[2 * p][1],
                            bhi[2 * p + 1][0], bhi[2 * p + 1][1], bH + addr);
                    LDSM_X4(blo[2 * p][0], blo[2 * p][1],
                            blo[2 * p + 1][0], blo[2 * p + 1][1], bL + addr);
                }
            }
            // term-outermost: RAW distance per accumulator = 16 MMAs
            #pragma unroll
            for (int f = 0; f < 2; f++)
                #pragma unroll
                for (int n = 0; n < 8; n++)
                    MMA_BF16(acc[f][n], ahi[f], bhi[n]);
            #pragma unroll
            for (int f = 0; f < 2; f++)
                #pragma unroll
                for (int n = 0; n < 8; n++)
                    MMA_BF16(acc[f][n], ahi[f], blo[n]);
            #pragma unroll
            for (int f = 0; f < 2; f++)
                #pragma unroll
                for (int n = 0; n < 8; n++)
                    MMA_BF16(acc[f][n], alo[f], bhi[n]);
        }
        __syncthreads();
    }

    // ---- epilogue ----
    #pragma unroll
    for (int f = 0; f < 2; f++) {
        const long r0 = (long)m0 + wm * 32 + f * 16 + (lane >> 2);
        #pragma unroll
        for (int n = 0; n < 8; n++) {
            const long col = (long)n0 + wn * 64 + n * 8 + (lane & 3) * 2;
            float v0 = acc[f][n][0] * alpha, v1 = acc[f][n][1] * alpha;
            float v2 = acc[f][n][2] * alpha, v3 = acc[f][n][3] * alpha;
            if (EPI == 0) {
                float* cp = C + (long)bz * sC;
                *(float2*)(cp + r0 * N + col)       = make_float2(v0, v1);
                *(float2*)(cp + (r0 + 8) * N + col) = make_float2(v2, v3);
            } else {
                uint32_t h0, l0, h1, l1;
                split_pack2(v0, v1, h0, l0);
                split_pack2(v2, v3, h1, l1);
                bf16* chp = Chi + (long)bz * sC;
                bf16* clp = Clo + (long)bz * sC;
                *(uint32_t*)(chp + r0 * N + col)       = h0;
                *(uint32_t*)(clp + r0 * N + col)       = l0;
                *(uint32_t*)(chp + (r0 + 8) * N + col) = h1;
                *(uint32_t*)(clp + (r0 + 8) * N + col) = l1;
            }
        }
    }
}

// ---------------------------------------------------------------------------
// elementwise split: fp32 -> bf16 hi/lo planes (float4 per thread)
// ---------------------------------------------------------------------------
__global__ __launch_bounds__(256)
void split_f32(const float* __restrict__ in, bf16* __restrict__ hi,
               bf16* __restrict__ lo, long n4)
{
    long i = (long)blockIdx.x * blockDim.x + threadIdx.x;
    if (i >= n4) return;
    float4 v = ((const float4*)in)[i];
    uint2 h, l;
    split_pack2(v.x, v.y, h.x, l.x);
    split_pack2(v.z, v.w, h.y, l.y);
    ((uint2*)hi)[i] = h;
    ((uint2*)lo)[i] = l;
}

// ---------------------------------------------------------------------------
// transpose + split: in fp32 [R,C] -> out hi/lo bf16 [C,R]
// ---------------------------------------------------------------------------
__global__ void transpose_split(const float* __restrict__ in,
                                bf16* __restrict__ ohi, bf16* __restrict__ olo,
                                int R, int C, long sIn, long sOut)
{
    __shared__ float t[32][33];
    const long b = blockIdx.z;
    in  += b * sIn;
    ohi += b * sOut;
    olo += b * sOut;
    const int c0 = blockIdx.x * 32, r0 = blockIdx.y * 32;
    #pragma unroll
    for (int i = threadIdx.y; i < 32; i += 8)
        t[i][threadIdx.x] = in[(long)(r0 + i) * C + c0 + threadIdx.x];
    __syncthreads();
    #pragma unroll
    for (int i = threadIdx.y; i < 32; i += 8) {
        float v = t[threadIdx.x][i];
        bf16 h = __float2bfloat16(v);
        bf16 l = __float2bfloat16(v - __bfloat162float(h));
        ohi[(long)(c0 + i) * R + r0 + threadIdx.x] = h;
        olo[(long)(c0 + i) * R + r0 + threadIdx.x] = l;
    }
}

// ---------------------------------------------------------------------------
// bf16 plane transpose: out[C,R] = in[R,C]^T for hi and lo planes
// ---------------------------------------------------------------------------
__global__ void transpose_bf16(const bf16* __restrict__ ihi, const bf16* __restrict__ ilo,
                               bf16* __restrict__ ohi, bf16* __restrict__ olo,
                               int R, int C, long sIn, long sOut)
{
    __shared__ bf16 th[32][33];
    __shared__ bf16 tl[32][33];
    const long b = blockIdx.z;
    ihi += b * sIn;  ilo += b * sIn;
    ohi += b * sOut; olo += b * sOut;
    const int c0 = blockIdx.x * 32, r0 = blockIdx.y * 32;
    #pragma unroll
    for (int i = threadIdx.y; i < 32; i += 8) {
        th[i][threadIdx.x] = ihi[(long)(r0 + i) * C + c0 + threadIdx.x];
        tl[i][threadIdx.x] = ilo[(long)(r0 + i) * C + c0 + threadIdx.x];
    }
    __syncthreads();
    #pragma unroll
    for (int i = threadIdx.y; i < 32; i += 8) {
        ohi[(long)(c0 + i) * R + r0 + threadIdx.x] = th[threadIdx.x][i];
        olo[(long)(c0 + i) * R + r0 + threadIdx.x] = tl[threadIdx.x][i];
    }
}

// ---------------------------------------------------------------------------
// Causal row softmax: S fp32 -> P hi/lo bf16 planes + zero tail
// ---------------------------------------------------------------------------
__global__ __launch_bounds__(256)
void softmax_split(float* __restrict__ S, bf16* __restrict__ Phi,
                   bf16* __restrict__ Plo)
{
    const int row = blockIdx.x;
    const int b   = blockIdx.y;
    const long base = ((long)b * SEQ + row) * SEQ;
    float* s = S + base;
    bf16* ph = Phi + base;
    bf16* pl = Plo + base;
    const int L = row + 1;

    __shared__ float sh[32];
    const int lane = threadIdx.x & 31;
    const int warp = threadIdx.x >> 5;
    const int nwarps = blockDim.x >> 5;

    float m = -INFINITY;
    for (int j = threadIdx.x; j < L; j += blockDim.x) m = fmaxf(m, s[j]);
    #pragma unroll
    for (int o = 16; o > 0; o >>= 1) m = fmaxf(m, __shfl_xor_sync(0xffffffffu, m, o));
    if (lane == 0) sh[warp] = m;
    __syncthreads();
    if (warp == 0) {
        float v = (lane < nwarps) ? sh[lane] : -INFINITY;
        #pragma unroll
        for (int o = 16; o > 0; o >>= 1) v = fmaxf(v, __shfl_xor_sync(0xffffffffu, v, o));
        if (lane == 0) sh[0] = v;
    }
    __syncthreads();
    m = sh[0];
    __syncthreads();

    float sum = 0.0f;
    for (int j = threadIdx.x; j < L; j += blockDim.x) {
        float e = __expf(s[j] - m);
        s[j] = e;
        sum += e;
    }
    #pragma unroll
    for (int o = 16; o > 0; o >>= 1) sum += __shfl_xor_sync(0xffffffffu, sum, o);
    if (lane == 0) sh[warp] = sum;
    __syncthreads();
    if (warp == 0) {
        float v = (lane < nwarps) ? sh[lane] : 0.0f;
        #pragma unroll
        for (int o = 16; o > 0; o >>= 1) v += __shfl_xor_sync(0xffffffffu, v, o);
        if (lane == 0) sh[0] = v;
    }
    __syncthreads();
    const float inv = 1.0f / sh[0];

    for (int j = threadIdx.x; j < L; j += blockDim.x) {
        float p = s[j] * inv;
        bf16 h = __float2bfloat16(p);
        bf16 l = __float2bfloat16(p - __bfloat162float(h));
        ph[j] = h;
        pl[j] = l;
    }
    const bf16 z = __float2bfloat16(0.0f);
    for (int j = L + threadIdx.x; j < SEQ; j += blockDim.x) { ph[j] = z; pl[j] = z; }
}

// ---------------------------------------------------------------------------
extern "C" void kernel_launch(void* const* d_in, const int* in_sizes, int n_in,
                              void* d_out, int out_size)
{
    const float* x  = (const float*)d_in[0];
    const float* Wq = (const float*)d_in[1];
    const float* Wk = (const float*)d_in[2];
    const float* Wv = (const float*)d_in[3];
    float* out = (float*)d_out;

    bf16 *xhi, *xlo, *Whi, *Wlo, *QKVhi, *QKVlo, *VThi, *VTlo, *Phi, *Plo;
    float *S;
    cudaGetSymbolAddress((void**)&xhi,   g_xhi);
    cudaGetSymbolAddress((void**)&xlo,   g_xlo);
    cudaGetSymbolAddress((void**)&Whi,   g_Whi);
    cudaGetSymbolAddress((void**)&Wlo,   g_Wlo);
    cudaGetSymbolAddress((void**)&QKVhi, g_QKVhi);
    cudaGetSymbolAddress((void**)&QKVlo, g_QKVlo);
    cudaGetSymbolAddress((void**)&VThi,  g_VThi);
    cudaGetSymbolAddress((void**)&VTlo,  g_VTlo);
    cudaGetSymbolAddress((void**)&S,     g_S);
    cudaGetSymbolAddress((void**)&Phi,   g_Phi);
    cudaGetSymbolAddress((void**)&Plo,   g_Plo);

    cudaFuncSetAttribute((const void*)mm_s<false, false, 1>,
                         cudaFuncAttributeMaxDynamicSharedMemorySize, SMEM_TOTAL);
    cudaFuncSetAttribute((const void*)mm_s<true, false, 0>,
                         cudaFuncAttributeMaxDynamicSharedMemorySize, SMEM_TOTAL);
    cudaFuncSetAttribute((const void*)mm_s<false, true, 0>,
                         cudaFuncAttributeMaxDynamicSharedMemorySize, SMEM_TOTAL);

    const long WP = (long)DIM * DIM;

    // 0) split x; transpose+split W
    split_f32<<<(unsigned)((PLANE / 4 + 255) / 256), 256>>>(x, xhi, xlo, PLANE / 4);
    {
        dim3 blk(32, 8), grd(DIM / 32, DIM / 32, 1);
        transpose_split<<<grd, blk>>>(Wq, Whi + 0 * WP, Wlo + 0 * WP, DIM, DIM, 0, 0);
        transpose_split<<<grd, blk>>>(Wk, Whi + 1 * WP, Wlo + 1 * WP, DIM, DIM, 0, 0);
        transpose_split<<<grd, blk>>>(Wv, Whi + 2 * WP, Wlo + 2 * WP, DIM, DIM, 0, 0);
    }

    // 1) Q,K,V projections -> split planes (single launch, z = 0,1,2)
    {
        dim3 grd(DIM / BN, (BATCH * SEQ) / BM, 3);
        mm_s<false, false, 1><<<grd, NTH, SMEM_TOTAL>>>(
            xhi, xlo, Whi, Wlo, nullptr, QKVhi, QKVlo,
            DIM, DIM, 1.0f, 0, WP, PLANE);
    }

    // 2) V^T per batch -> split planes [DIM, SEQ] (bf16 in/out, exact)
    {
        dim3 blk(32, 8), grd(DIM / 32, SEQ / 32, BATCH);
        transpose_bf16<<<grd, blk>>>(QKVhi + 2 * PLANE, QKVlo + 2 * PLANE,
                                     VThi, VTlo, SEQ, DIM,
                                     (long)SEQ * DIM, (long)SEQ * DIM);
    }

    // 3) S = Q K^T * scale (causal block-skip), fp32 out
    {
        dim3 grd(SEQ / BN, SEQ / BM, BATCH);
        mm_s<true, false, 0><<<grd, NTH, SMEM_TOTAL>>>(
            QKVhi, QKVlo, QKVhi + PLANE, QKVlo + PLANE, S, nullptr, nullptr,
            SEQ, DIM, 1.0f / sqrtf((float)DIM),
            (long)SEQ * DIM, (long)SEQ * DIM, (long)SEQ * SEQ);
    }

    // 4) softmax -> P split planes (+ zero tail)
    {
        dim3 grd(SEQ, BATCH, 1);
        softmax_split<<<grd, 256>>>(S, Phi, Plo);
    }

    // 5) out = P V (K-chunks causally limited), fp32 out
    {
        dim3 grd(DIM / BN, SEQ / BM, BATCH);
        mm_s<false, true, 0><<<grd, NTH, SMEM_TOTAL>>>(
            Phi, Plo, VThi, VTlo, out, nullptr, nullptr,
            DIM, SEQ, 1.0f,
            (long)SEQ * SEQ, (long)SEQ * DIM, (long)SEQ * DIM);
    }
}

// round 9
// speedup vs baseline: 1.0380x; 1.0380x over previous
#include <cuda_runtime.h>
#include <cuda_bf16.h>
#include <math.h>
#include <stdint.h>

// Problem constants
#define BATCH 4
#define SEQ   2048
#define DIM   1024

// GEMM tiling: CTA 256x128x32, 8 warps (4m x 2n), warp tile 64x64, double buffer
#define BM 256
#define BN 128
#define BK 32
#define NTH 256

// smem: bf16 tiles, rows padded to 40 elems (80 B) for conflict-free ldmatrix
#define RSB      80
#define ATILE_B  (256 * RSB)             // 20480 B per A plane tile
#define BTILE_B  (128 * RSB)             // 10240 B per B plane tile
#define OFF_AHI  0
#define OFF_ALO  (ATILE_B)
#define OFF_BHI  (2 * ATILE_B)
#define OFF_BLO  (2 * ATILE_B + BTILE_B)
#define STAGE_B  (2 * ATILE_B + 2 * BTILE_B)   // 61440 B
#define SMEM_TOTAL (2 * STAGE_B)               // 122880 B

typedef __nv_bfloat16 bf16;

// ---------------------------------------------------------------------------
// Scratch (device globals — allocation-free per harness rules)
// ---------------------------------------------------------------------------
#define PLANE  ((long)BATCH * SEQ * DIM)     // 8M elems
__device__ bf16  g_xhi[PLANE],  g_xlo[PLANE];
__device__ bf16  g_Whi[3 * DIM * DIM], g_Wlo[3 * DIM * DIM];
__device__ bf16  g_QKVhi[3 * PLANE], g_QKVlo[3 * PLANE];   // Q | K | V planes
__device__ bf16  g_VThi[PLANE], g_VTlo[PLANE];             // per batch [DIM, SEQ]
__device__ float g_S[(size_t)BATCH * SEQ * SEQ];
__device__ bf16  g_Phi[(size_t)BATCH * SEQ * SEQ], g_Plo[(size_t)BATCH * SEQ * SEQ];

// ---------------------------------------------------------------------------
// helpers
// ---------------------------------------------------------------------------
__device__ __forceinline__ uint32_t smem_u32(const void* p) {
    uint32_t a;
    asm("{ .reg .u64 t; cvta.to.shared.u64 t, %1; cvt.u32.u64 %0, t; }"
        : "=r"(a) : "l"(p));
    return a;
}

__device__ __forceinline__ void cpa16(uint32_t dst, const void* src) {
    asm volatile("cp.async.cg.shared.global [%0], [%1], 16;"
                 :: "r"(dst), "l"(src) : "memory");
}
#define CP_COMMIT() asm volatile("cp.async.commit_group;" ::: "memory")
#define CP_WAIT(n)  asm volatile("cp.async.wait_group %0;" :: "n"(n) : "memory")

#define LDSM_X4(r0, r1, r2, r3, addr) \
    asm volatile("ldmatrix.sync.aligned.m8n8.x4.shared.b16 {%0,%1,%2,%3}, [%4];" \
                 : "=r"(r0), "=r"(r1), "=r"(r2), "=r"(r3) : "r"(addr))

#define MMA_BF16(d, a, b) \
    asm volatile("mma.sync.aligned.m16n8k16.row.col.f32.bf16.bf16.f32 " \
                 "{%0,%1,%2,%3}, {%4,%5,%6,%7}, {%8,%9}, {%0,%1,%2,%3};" \
                 : "+f"((d)[0]), "+f"((d)[1]), "+f"((d)[2]), "+f"((d)[3]) \
                 : "r"((a)[0]), "r"((a)[1]), "r"((a)[2]), "r"((a)[3]), \
                   "r"((b)[0]), "r"((b)[1]))

// split 2 floats -> packed bf16x2 (hi) and packed bf16x2 (lo residual)
__device__ __forceinline__ void split_pack2(float a, float b,
                                            uint32_t& hi, uint32_t& lo) {
    __nv_bfloat162 h = __floats2bfloat162_rn(a, b);
    float2 hf = __bfloat1622float2(h);
    __nv_bfloat162 l = __floats2bfloat162_rn(a - hf.x, b - hf.y);
    hi = *reinterpret_cast<uint32_t*>(&h);
    lo = *reinterpret_cast<uint32_t*>(&l);
}

// ---------------------------------------------------------------------------
// bf16 split GEMM (pre-split inputs), double-buffered cp.async:
//   C[M,N] = alpha * (Ahi+Alo)[M,K] * (Bhi+Blo)[N,K]^T   (lo*lo dropped)
// CTA 256x128; 8 warps as 4(m) x 2(n), each 64x64.
// EPI 0: C fp32;  EPI 1: C written as hi/lo bf16 planes.
// CSKIP: skip tiles above causal diagonal. KLIM: K chunks < m0+BM.
// ---------------------------------------------------------------------------
template <bool CSKIP, bool KLIM, int EPI>
__global__ __launch_bounds__(NTH, 1)
void mm_s(const bf16* __restrict__ Ahi, const bf16* __restrict__ Alo,
          const bf16* __restrict__ Bhi, const bf16* __restrict__ Blo,
          float* __restrict__ C, bf16* __restrict__ Chi, bf16* __restrict__ Clo,
          int N, int K, float alpha, long sA, long sB, long sC)
{
    const int bz = blockIdx.z;
    Ahi += (long)bz * sA;  Alo += (long)bz * sA;
    Bhi += (long)bz * sB;  Blo += (long)bz * sB;

    const int m0 = blockIdx.y * BM;
    const int n0 = blockIdx.x * BN;
    if (CSKIP && (m0 + BM - 1 < n0)) return;

    int nch = K / BK;
    if (KLIM) {
        int lim = (m0 + BM) / BK;
        nch = (lim < nch) ? lim : nch;
    }

    extern __shared__ char smem[];
    const uint32_t sb = smem_u32(smem);

    const int tid  = threadIdx.x;
    const int wid  = tid >> 5;
    const int lane = tid & 31;
    const int wm   = wid & 3;       // warp m block (64 rows): 4 blocks = 256
    const int wn   = wid >> 2;      // warp n block (64 cols): 2 blocks = 128

    // cp.async: A plane 1024 16B-chunks (4/thread), B plane 512 (2/thread)
    const int rc = tid >> 2;             // 0..63
    const int oc = tid & 3;

    auto stage_load = [&](int c, int buf) {
        const uint32_t st = sb + buf * STAGE_B;
        const long ck = (long)c * BK + oc * 8;
        #pragma unroll
        for (int i = 0; i < 4; i++) {
            const int row = rc + i * 64;                 // 0..255
            const long g = (long)(m0 + row) * K + ck;
            const uint32_t d = row * RSB + oc * 16;
            cpa16(st + OFF_AHI + d, Ahi + g);
            cpa16(st + OFF_ALO + d, Alo + g);
        }
        #pragma unroll
        for (int i = 0; i < 2; i++) {
            const int row = rc + i * 64;                 // 0..127
            const long g = (long)(n0 + row) * K + ck;
            const uint32_t d = row * RSB + oc * 16;
            cpa16(st + OFF_BHI + d, Bhi + g);
            cpa16(st + OFF_BLO + d, Blo + g);
        }
        CP_COMMIT();
    };

    float acc[4][8][4] = {};

    stage_load(0, 0);

    for (int c = 0; c < nch; c++) {
        const int buf = c & 1;
        if (c + 1 < nch) { stage_load(c + 1, buf ^ 1); CP_WAIT(1); }
        else             { CP_WAIT(0); }
        __syncthreads();

        const uint32_t st = sb + buf * STAGE_B;
        const uint32_t aH = st + OFF_AHI;
        const uint32_t aL = st + OFF_ALO;
        const uint32_t bH = st + OFF_BHI;
        const uint32_t bL = st + OFF_BLO;

        #pragma unroll
        for (int kk = 0; kk < BK; kk += 16) {
            // A fragments: 4 m16 blocks, hi + lo
            uint32_t ahi[4][4], alo[4][4];
            {
                const int arow = wm * 64 + (lane & 15);
                const int akb  = (kk + ((lane >> 4) << 3)) * 2;
                #pragma unroll
                for (int f = 0; f < 4; f++) {
                    const uint32_t addr = (uint32_t)((arow + f * 16) * RSB + akb);
                    LDSM_X4(ahi[f][0], ahi[f][1], ahi[f][2], ahi[f][3], aH + addr);
                    LDSM_X4(alo[f][0], alo[f][1], alo[f][2], alo[f][3], aL + addr);
                }
            }
            // B: 4 n16 pairs; per pair load hi+lo, then 24 split MMAs
            const int g = lane >> 3;
            const int r = lane & 7;
            const int brow0 = wn * 64 + ((g >> 1) << 3) + r;
            const int bkb   = (kk + ((g & 1) << 3)) * 2;
            #pragma unroll
            for (int p = 0; p < 4; p++) {
                uint32_t bhi[2][2], blo[2][2];
                const uint32_t addr = (uint32_t)((brow0 + p * 16) * RSB + bkb);
                LDSM_X4(bhi[0][0], bhi[0][1], bhi[1][0], bhi[1][1], bH + addr);
                LDSM_X4(blo[0][0], blo[0][1], blo[1][0], blo[1][1], bL + addr);
                #pragma unroll
                for (int f = 0; f < 4; f++) {
                    #pragma unroll
                    for (int q = 0; q < 2; q++) {
                        const int n = 2 * p + q;
                        MMA_BF16(acc[f][n], ahi[f], bhi[q]);
                        MMA_BF16(acc[f][n], ahi[f], blo[q]);
                        MMA_BF16(acc[f][n], alo[f], bhi[q]);
                    }
                }
            }
        }
        __syncthreads();
    }

    // ---- epilogue ----
    #pragma unroll
    for (int f = 0; f < 4; f++) {
        const long r0 = (long)m0 + wm * 64 + f * 16 + (lane >> 2);
        #pragma unroll
        for (int n = 0; n < 8; n++) {
            const long col = (long)n0 + wn * 64 + n * 8 + (lane & 3) * 2;
            float v0 = acc[f][n][0] * alpha, v1 = acc[f][n][1] * alpha;
            float v2 = acc[f][n][2] * alpha, v3 = acc[f][n][3] * alpha;
            if (EPI == 0) {
                float* cp = C + (long)bz * sC;
                *(float2*)(cp + r0 * N + col)       = make_float2(v0, v1);
                *(float2*)(cp + (r0 + 8) * N + col) = make_float2(v2, v3);
            } else {
                uint32_t h0, l0, h1, l1;
                split_pack2(v0, v1, h0, l0);
                split_pack2(v2, v3, h1, l1);
                bf16* chp = Chi + (long)bz * sC;
                bf16* clp = Clo + (long)bz * sC;
                *(uint32_t*)(chp + r0 * N + col)       = h0;
                *(uint32_t*)(clp + r0 * N + col)       = l0;
                *(uint32_t*)(chp + (r0 + 8) * N + col) = h1;
                *(uint32_t*)(clp + (r0 + 8) * N + col) = l1;
            }
        }
    }
}

// ---------------------------------------------------------------------------
// elementwise split: fp32 -> bf16 hi/lo planes (float4 per thread)
// ---------------------------------------------------------------------------
__global__ __launch_bounds__(256)
void split_f32(const float* __restrict__ in, bf16* __restrict__ hi,
               bf16* __restrict__ lo, long n4)
{
    long i = (long)blockIdx.x * blockDim.x + threadIdx.x;
    if (i >= n4) return;
    float4 v = ((const float4*)in)[i];
    uint2 h, l;
    split_pack2(v.x, v.y, h.x, l.x);
    split_pack2(v.z, v.w, h.y, l.y);
    ((uint2*)hi)[i] = h;
    ((uint2*)lo)[i] = l;
}

// ---------------------------------------------------------------------------
// transpose + split: in fp32 [R,C] -> out hi/lo bf16 [C,R]
// ---------------------------------------------------------------------------
__global__ void transpose_split(const float* __restrict__ in,
                                bf16* __restrict__ ohi, bf16* __restrict__ olo,
                                int R, int C, long sIn, long sOut)
{
    __shared__ float t[32][33];
    const long b = blockIdx.z;
    in  += b * sIn;
    ohi += b * sOut;
    olo += b * sOut;
    const int c0 = blockIdx.x * 32, r0 = blockIdx.y * 32;
    #pragma unroll
    for (int i = threadIdx.y; i < 32; i += 8)
        t[i][threadIdx.x] = in[(long)(r0 + i) * C + c0 + threadIdx.x];
    __syncthreads();
    #pragma unroll
    for (int i = threadIdx.y; i < 32; i += 8) {
        float v = t[threadIdx.x][i];
        bf16 h = __float2bfloat16(v);
        bf16 l = __float2bfloat16(v - __bfloat162float(h));
        ohi[(long)(c0 + i) * R + r0 + threadIdx.x] = h;
        olo[(long)(c0 + i) * R + r0 + threadIdx.x] = l;
    }
}

// ---------------------------------------------------------------------------
// bf16 plane transpose: out[C,R] = in[R,C]^T for hi and lo planes
// ---------------------------------------------------------------------------
__global__ void transpose_bf16(const bf16* __restrict__ ihi, const bf16* __restrict__ ilo,
                               bf16* __restrict__ ohi, bf16* __restrict__ olo,
                               int R, int C, long sIn, long sOut)
{
    __shared__ bf16 th[32][33];
    __shared__ bf16 tl[32][33];
    const long b = blockIdx.z;
    ihi += b * sIn;  ilo += b * sIn;
    ohi += b * sOut; olo += b * sOut;
    const int c0 = blockIdx.x * 32, r0 = blockIdx.y * 32;
    #pragma unroll
    for (int i = threadIdx.y; i < 32; i += 8) {
        th[i][threadIdx.x] = ihi[(long)(r0 + i) * C + c0 + threadIdx.x];
        tl[i][threadIdx.x] = ilo[(long)(r0 + i) * C + c0 + threadIdx.x];
    }
    __syncthreads();
    #pragma unroll
    for (int i = threadIdx.y; i < 32; i += 8) {
        ohi[(long)(c0 + i) * R + r0 + threadIdx.x] = th[threadIdx.x][i];
        olo[(long)(c0 + i) * R + r0 + threadIdx.x] = tl[threadIdx.x][i];
    }
}

// ---------------------------------------------------------------------------
// Causal row softmax: S fp32 -> P hi/lo bf16 planes + zero tail
// ---------------------------------------------------------------------------
__global__ __launch_bounds__(256)
void softmax_split(float* __restrict__ S, bf16* __restrict__ Phi,
                   bf16* __restrict__ Plo)
{
    const int row = blockIdx.x;
    const int b   = blockIdx.y;
    const long base = ((long)b * SEQ + row) * SEQ;
    float* s = S + base;
    bf16* ph = Phi + base;
    bf16* pl = Plo + base;
    const int L = row + 1;

    __shared__ float sh[32];
    const int lane = threadIdx.x & 31;
    const int warp = threadIdx.x >> 5;
    const int nwarps = blockDim.x >> 5;

    float m = -INFINITY;
    for (int j = threadIdx.x; j < L; j += blockDim.x) m = fmaxf(m, s[j]);
    #pragma unroll
    for (int o = 16; o > 0; o >>= 1) m = fmaxf(m, __shfl_xor_sync(0xffffffffu, m, o));
    if (lane == 0) sh[warp] = m;
    __syncthreads();
    if (warp == 0) {
        float v = (lane < nwarps) ? sh[lane] : -INFINITY;
        #pragma unroll
        for (int o = 16; o > 0; o >>= 1) v = fmaxf(v, __shfl_xor_sync(0xffffffffu, v, o));
        if (lane == 0) sh[0] = v;
    }
    __syncthreads();
    m = sh[0];
    __syncthreads();

    float sum = 0.0f;
    for (int j = threadIdx.x; j < L; j += blockDim.x) {
        float e = __expf(s[j] - m);
        s[j] = e;
        sum += e;
    }
    #pragma unroll
    for (int o = 16; o > 0; o >>= 1) sum += __shfl_xor_sync(0xffffffffu, sum, o);
    if (lane == 0) sh[warp] = sum;
    __syncthreads();
    if (warp == 0) {
        float v = (lane < nwarps) ? sh[lane] : 0.0f;
        #pragma unroll
        for (int o = 16; o > 0; o >>= 1) v += __shfl_xor_sync(0xffffffffu, v, o);
        if (lane == 0) sh[0] = v;
    }
    __syncthreads();
    const float inv = 1.0f / sh[0];

    for (int j = threadIdx.x; j < L; j += blockDim.x) {
        float p = s[j] * inv;
        bf16 h = __float2bfloat16(p);
        bf16 l = __float2bfloat16(p - __bfloat162float(h));
        ph[j] = h;
        pl[j] = l;
    }
    const bf16 z = __float2bfloat16(0.0f);
    for (int j = L + threadIdx.x; j < SEQ; j += blockDim.x) { ph[j] = z; pl[j] = z; }
}

// ---------------------------------------------------------------------------
extern "C" void kernel_launch(void* const* d_in, const int* in_sizes, int n_in,
                              void* d_out, int out_size)
{
    const float* x  = (const float*)d_in[0];
    const float* Wq = (const float*)d_in[1];
    const float* Wk = (const float*)d_in[2];
    const float* Wv = (const float*)d_in[3];
    float* out = (float*)d_out;

    bf16 *xhi, *xlo, *Whi, *Wlo, *QKVhi, *QKVlo, *VThi, *VTlo, *Phi, *Plo;
    float *S;
    cudaGetSymbolAddress((void**)&xhi,   g_xhi);
    cudaGetSymbolAddress((void**)&xlo,   g_xlo);
    cudaGetSymbolAddress((void**)&Whi,   g_Whi);
    cudaGetSymbolAddress((void**)&Wlo,   g_Wlo);
    cudaGetSymbolAddress((void**)&QKVhi, g_QKVhi);
    cudaGetSymbolAddress((void**)&QKVlo, g_QKVlo);
    cudaGetSymbolAddress((void**)&VThi,  g_VThi);
    cudaGetSymbolAddress((void**)&VTlo,  g_VTlo);
    cudaGetSymbolAddress((void**)&S,     g_S);
    cudaGetSymbolAddress((void**)&Phi,   g_Phi);
    cudaGetSymbolAddress((void**)&Plo,   g_Plo);

    cudaFuncSetAttribute((const void*)mm_s<false, false, 1>,
                         cudaFuncAttributeMaxDynamicSharedMemorySize, SMEM_TOTAL);
    cudaFuncSetAttribute((const void*)mm_s<true, false, 0>,
                         cudaFuncAttributeMaxDynamicSharedMemorySize, SMEM_TOTAL);
    cudaFuncSetAttribute((const void*)mm_s<false, true, 0>,
                         cudaFuncAttributeMaxDynamicSharedMemorySize, SMEM_TOTAL);

    const long WP = (long)DIM * DIM;

    // 0) split x in TWO launches (so the QKV GEMM is the 6th launch and gets
    //    captured by ncu's -s 5 -c 1); transpose+split W
    {
        const long half = PLANE / 2;                 // elems
        const long n4h  = half / 4;                  // float4 per half
        split_f32<<<(unsigned)((n4h + 255) / 256), 256>>>(x, xhi, xlo, n4h);
        split_f32<<<(unsigned)((n4h + 255) / 256), 256>>>(x + half, xhi + half,
                                                          xlo + half, n4h);
    }
    {
        dim3 blk(32, 8), grd(DIM / 32, DIM / 32, 1);
        transpose_split<<<grd, blk>>>(Wq, Whi + 0 * WP, Wlo + 0 * WP, DIM, DIM, 0, 0);
        transpose_split<<<grd, blk>>>(Wk, Whi + 1 * WP, Wlo + 1 * WP, DIM, DIM, 0, 0);
        transpose_split<<<grd, blk>>>(Wv, Whi + 2 * WP, Wlo + 2 * WP, DIM, DIM, 0, 0);
    }

    // 1) Q,K,V projections -> split planes (launch #6, profiled by ncu)
    {
        dim3 grd(DIM / BN, (BATCH * SEQ) / BM, 3);
        mm_s<false, false, 1><<<grd, NTH, SMEM_TOTAL>>>(
            xhi, xlo, Whi, Wlo, nullptr, QKVhi, QKVlo,
            DIM, DIM, 1.0f, 0, WP, PLANE);
    }

    // 2) V^T per batch -> split planes [DIM, SEQ] (bf16 in/out, exact)
    {
        dim3 blk(32, 8), grd(DIM / 32, SEQ / 32, BATCH);
        transpose_bf16<<<grd, blk>>>(QKVhi + 2 * PLANE, QKVlo + 2 * PLANE,
                                     VThi, VTlo, SEQ, DIM,
                                     (long)SEQ * DIM, (long)SEQ * DIM);
    }

    // 3) S = Q K^T * scale (causal block-skip), fp32 out
    {
        dim3 grd(SEQ / BN, SEQ / BM, BATCH);
        mm_s<true, false, 0><<<grd, NTH, SMEM_TOTAL>>>(
            QKVhi, QKVlo, QKVhi + PLANE, QKVlo + PLANE, S, nullptr, nullptr,
            SEQ, DIM, 1.0f / sqrtf((float)DIM),
            (long)SEQ * DIM, (long)SEQ * DIM, (long)SEQ * SEQ);
    }

    // 4) softmax -> P split planes (+ zero tail)
    {
        dim3 grd(SEQ, BATCH, 1);
        softmax_split<<<grd, 256>>>(S, Phi, Plo);
    }

    // 5) out = P V (K-chunks causally limited), fp32 out
    {
        dim3 grd(DIM / BN, SEQ / BM, BATCH);
        mm_s<false, true, 0><<<grd, NTH, SMEM_TOTAL>>>(
            Phi, Plo, VThi, VTlo, out, nullptr, nullptr,
            DIM, SEQ, 1.0f,
            (long)SEQ * SEQ, (long)SEQ * DIM, (long)SEQ * DIM);
    }
}